// round 5
// baseline (speedup 1.0000x reference)
#include <cuda_runtime.h>

// PSF patch renderer, tile-privatized.
// Output: B=128 images of 512x512 f32. S=1024 Gaussian-ERF 6x6 patches/image.
// Grid = (32 tiles, 128 images), 256 threads. Each CTA owns a 64x128 tile:
//   1) zero 32KB smem tile
//   2) scan the image's 1024 points; patches intersecting the tile are
//      rendered (14 erfs) and accumulated via smem atomicAdd (cheap ATOMS)
//   3) coalesced float4 STG of the tile (doubles as the zero-fill)
// No global atomics anywhere -> removes the ~24us/SM RED.E.ADD issue tax
// seen in the round-4 profile (dram 32%, issue 4.2%: RED-serialization-bound).

#define NXC 512
#define NYC 512
#define PHW 3
#define PP  6
#define BB  128
#define SS  1024
#define TR  64      // tile rows (x-dimension)
#define TC  128     // tile cols (y-dimension)
#define NT  256     // threads per CTA

__global__ __launch_bounds__(NT)
void psf_tile_kernel(const float* __restrict__ z, float* __restrict__ out) {
    __shared__ float tile[TR * TC];   // 32 KB

    const int b   = blockIdx.y;
    const int tr  = blockIdx.x >> 2;          // 0..7  (8 row-tiles of 64)
    const int tc  = blockIdx.x & 3;           // 0..3  (4 col-tiles of 128)
    const int r0  = tr * TR;
    const int c0  = tc * TC;
    const int tid = threadIdx.x;

    // ---- 1) zero smem tile ----
    float4* t4 = reinterpret_cast<float4*>(tile);
    const float4 zero4 = make_float4(0.f, 0.f, 0.f, 0.f);
    #pragma unroll
    for (int i = 0; i < (TR * TC / 4) / NT; i++)    // 8 iters
        t4[tid + i * NT] = zero4;
    __syncthreads();

    // ---- 2) scan points, accumulate intersecting patches ----
    const float* zx = z + b * (2 * SS);
    const float* zy = zx + SS;
    const float inv_alpha = 1.0f / (1.41421356237309515f * 0.92f); // 1/(sqrt2*sigma)

    for (int p = tid; p < SS; p += NT) {            // 4 points/thread
        const float x0 = zx[p];
        const float y0 = zy[p];
        const int px = __float2int_rn(x0) - PHW;    // round-half-even, like jnp.round
        const int py = __float2int_rn(y0) - PHW;

        // patch-tile intersection (reject early, before erfs)
        if (px + PP <= r0 || px >= r0 + TR || py + PP <= c0 || py >= c0 + TC)
            continue;
        // validity (reference zeroes invalid patches)
        if (px < 0 || px >= NXC - PP || py < 0 || py >= NYC - PP)
            continue;

        const float x0p = x0 - (float)px;
        const float y0p = y0 - (float)py;

        float ex[PP + 1], ey[PP + 1];
        #pragma unroll
        for (int k = 0; k <= PP; k++) {
            const float bk = (float)k - 0.5f;
            ex[k] = erff((bk - x0p) * inv_alpha);
            ey[k] = erff((bk - y0p) * inv_alpha);
        }
        float lx[PP], ly[PP];
        #pragma unroll
        for (int k = 0; k < PP; k++) {
            lx[k] = 500.0f * (ex[k + 1] - ex[k]);   // fold i0=1000 and the 0.5
            ly[k] = 0.5f   * (ey[k + 1] - ey[k]);
        }

        #pragma unroll
        for (int i = 0; i < PP; i++) {
            const int r = px + i - r0;
            if ((unsigned)r >= TR) continue;
            const float lxi = lx[i];
            float* trow = tile + r * TC - c0;       // index by absolute col
            #pragma unroll
            for (int j = 0; j < PP; j++) {
                const int c = py + j;
                if ((unsigned)(c - c0) >= TC) continue;
                atomicAdd(trow + c, lxi * ly[j]);
            }
        }
    }
    __syncthreads();

    // ---- 3) coalesced tile writeback (also provides the zeros) ----
    float* gbase = out + (size_t)b * (NXC * NYC) + (size_t)r0 * NYC + c0;
    #pragma unroll
    for (int i = 0; i < (TR * TC / 4) / NT; i++) {  // 8 iters
        const int idx = tid + i * NT;               // float4 index, 0..2047
        const int r   = idx >> 5;                   // 32 float4 per 128-col row
        const int c4  = idx & 31;
        reinterpret_cast<float4*>(gbase + (size_t)r * NYC)[c4] = t4[idx];
    }
}

extern "C" void kernel_launch(void* const* d_in, const int* in_sizes, int n_in,
                              void* d_out, int out_size) {
    const float* z = (const float*)d_in[0];
    float* out = (float*)d_out;
    dim3 grid(32, BB);                               // 4096 CTAs
    psf_tile_kernel<<<grid, NT>>>(z, out);
}

// round 6
// speedup vs baseline: 1.7375x; 1.7375x over previous
#include <cuda_runtime.h>

// PSF patch renderer, two-phase:
//   K1 zero_kernel:    grid-stride float4 zero-fill of 128MB output (DRAM-floor).
//   K2 scatter_kernel: 1 thread per point (131072 total), 14 erfs, then the 6x6
//                      patch scattered with red.global.add.v2.f32 (4 per row,
//                      even-aligned, +0.0f padded -> no divergence, 24 REDs/patch).
// Sequential launches provide zero->scatter ordering; no barriers, all 148 SMs.

#define NXC 512
#define NYC 512
#define PHW 3
#define PP  6
#define BB  128
#define SS  1024

__global__ __launch_bounds__(256)
void zero_kernel(float4* __restrict__ out) {
    // 128 images * 512*512 floats = 8,388,608 float4 = 8192 blocks * 256 thr * 4
    const unsigned i = blockIdx.x * 256u + threadIdx.x;
    const float4 z4 = make_float4(0.f, 0.f, 0.f, 0.f);
    out[i]            = z4;
    out[i + 2097152u] = z4;
    out[i + 4194304u] = z4;
    out[i + 6291456u] = z4;
}

__device__ __forceinline__ void red2(float* p, float a, float b) {
    asm volatile("red.global.add.v2.f32 [%0], {%1, %2};"
                 :: "l"(p), "f"(a), "f"(b) : "memory");
}

__global__ __launch_bounds__(256)
void scatter_kernel(const float* __restrict__ z, float* __restrict__ out) {
    const int b = blockIdx.y;
    const int p = blockIdx.x * 256 + threadIdx.x;   // 0..1023

    const float x0 = z[b * (2 * SS) + p];
    const float y0 = z[b * (2 * SS) + SS + p];

    // jnp.round = round-half-to-even
    const int px = __float2int_rn(x0) - PHW;
    const int py = __float2int_rn(y0) - PHW;
    if (px < 0 || px >= NXC - PP || py < 0 || py >= NYC - PP)
        return;                                     // invalid -> contributes zero

    const float x0p = x0 - (float)px;
    const float y0p = y0 - (float)py;
    const float inv_alpha = 1.0f / (1.41421356237309515f * 0.92f);  // 1/(sqrt2*sigma)

    float ex[PP + 1], ey[PP + 1];
    #pragma unroll
    for (int k = 0; k <= PP; k++) {
        const float bk = (float)k - 0.5f;
        ex[k] = erff((bk - x0p) * inv_alpha);
        ey[k] = erff((bk - y0p) * inv_alpha);
    }
    float lx[PP], ly[PP];
    #pragma unroll
    for (int k = 0; k < PP; k++) {
        lx[k] = 500.0f * (ex[k + 1] - ex[k]);       // fold i0=1000 and the 0.5
        ly[k] = 0.5f   * (ey[k + 1] - ey[k]);
    }

    // Even-aligned 8-wide row window [py_al, py_al+8) covering [py, py+6),
    // padded with exact +0.0f. Always in-bounds: py <= 505 -> py_al+8 <= 512.
    const int pos   = py & 1;                       // 0 or 1
    const int py_al = py - pos;
    float w[8];
    #pragma unroll
    for (int k = 0; k < 8; k++) w[k] = 0.0f;
    #pragma unroll
    for (int j = 0; j < PP; j++) w[pos + j] = ly[j];

    float* img = out + (size_t)b * (NXC * NYC);
    #pragma unroll
    for (int i = 0; i < PP; i++) {
        float* row = img + (px + i) * NYC + py_al;  // 8B-aligned (py_al even)
        const float lxi = lx[i];
        red2(row + 0, lxi * w[0], lxi * w[1]);
        red2(row + 2, lxi * w[2], lxi * w[3]);
        red2(row + 4, lxi * w[4], lxi * w[5]);
        red2(row + 6, lxi * w[6], lxi * w[7]);
    }
}

extern "C" void kernel_launch(void* const* d_in, const int* in_sizes, int n_in,
                              void* d_out, int out_size) {
    const float* z = (const float*)d_in[0];
    float* out = (float*)d_out;
    zero_kernel<<<8192, 256>>>(reinterpret_cast<float4*>(out));
    scatter_kernel<<<dim3(4, BB), 256>>>(z, out);
}